// round 11
// baseline (speedup 1.0000x reference)
#include <cuda_runtime.h>
#include <cuda_fp16.h>
#include <cstdint>

#define Gn 4
#define Nn 50000
#define En 400000
#define Dn 128
#define Ln 3
#define NEx 8
#define AHn 64
#define ROWS (Gn*Nn)
#define EDGES (Gn*En)
#define NT128 ((ROWS + 127) / 128)
#define LN_EPS 1e-5f
#define NB_SCAN 782              // ceil(ROWS/256)

// ---------------- scratch (static, allocation-free) ----------------
__device__ float g_bufA[(size_t)ROWS * Dn];   // fp32 final-layer output (readout)
__device__ __half g_xh[(size_t)ROWS * Dn];    // fp16 current-layer features
__device__ __half g_hh[(size_t)ROWS * Dn];    // fp16 h = x + agg
__device__ float g_gvec[Gn * Dn];
__device__ uint32_t g_W1h[Ln * 8192];
__device__ uint32_t g_W2h[Ln * 8192];
// CSR scratch
__device__ int g_cnt[ROWS];
__device__ int g_off[ROWS];
__device__ int g_cur[ROWS];
__device__ int g_adj[EDGES];
__device__ int g_bsum[NB_SCAN];

__device__ __forceinline__ void mma_f16(float* c, uint32_t a0, uint32_t a1,
                                        uint32_t a2, uint32_t a3,
                                        uint32_t b0, uint32_t b1) {
    asm volatile(
        "mma.sync.aligned.m16n8k16.row.col.f32.f16.f16.f32 "
        "{%0,%1,%2,%3}, {%4,%5,%6,%7}, {%8,%9}, {%0,%1,%2,%3};"
        : "+f"(c[0]), "+f"(c[1]), "+f"(c[2]), "+f"(c[3])
        : "r"(a0), "r"(a1), "r"(a2), "r"(a3), "r"(b0), "r"(b1));
}

// ---------------- CSR build (unchanged) ----------------
__global__ void k_csr_zero() {
    int i = blockIdx.x * 256 + threadIdx.x;
    if (i < ROWS) g_cnt[i] = 0;
}
__global__ void k_csr_count(const int* __restrict__ ei) {
    int t = blockIdx.x * 256 + threadIdx.x;
    int g = t / En, e = t - g * En;
    int dst = ei[(size_t)g * 2 * En + En + e];
    atomicAdd(&g_cnt[g * Nn + dst], 1);
}
__global__ void k_scan_block() {
    __shared__ int s[256];
    int i = blockIdx.x * 256 + threadIdx.x;
    int v = (i < ROWS) ? g_cnt[i] : 0;
    s[threadIdx.x] = v;
    __syncthreads();
    #pragma unroll
    for (int o = 1; o < 256; o <<= 1) {
        int t = (threadIdx.x >= o) ? s[threadIdx.x - o] : 0;
        __syncthreads();
        s[threadIdx.x] += t;
        __syncthreads();
    }
    if (i < ROWS) g_off[i] = s[threadIdx.x] - v;
    if (threadIdx.x == 255) g_bsum[blockIdx.x] = s[255];
}
__global__ void k_scan_top() {
    __shared__ int s[1024];
    int tid = threadIdx.x;
    int v = (tid < NB_SCAN) ? g_bsum[tid] : 0;
    s[tid] = v;
    __syncthreads();
    #pragma unroll
    for (int o = 1; o < 1024; o <<= 1) {
        int t = (tid >= o) ? s[tid - o] : 0;
        __syncthreads();
        s[tid] += t;
        __syncthreads();
    }
    if (tid < NB_SCAN) g_bsum[tid] = s[tid] - v;
}
__global__ void k_scan_add() {
    int i = blockIdx.x * 256 + threadIdx.x;
    if (i < ROWS) {
        int o = g_off[i] + g_bsum[blockIdx.x];
        g_off[i] = o;
        g_cur[i] = o;
    }
}
__global__ void k_csr_fill(const int* __restrict__ ei) {
    int t = blockIdx.x * 256 + threadIdx.x;
    int g = t / En, e = t - g * En;
    const int* eig = ei + (size_t)g * 2 * En;
    int src = eig[e];
    int dst = eig[En + e];
    int pos = atomicAdd(&g_cur[g * Nn + dst], 1);
    g_adj[pos] = g * Nn + src;
}

// ---------------- fp16 conversion of the input features ----------------
__global__ void k_tohalf(const float* __restrict__ x0) {
    size_t i = (size_t)blockIdx.x * 256 + threadIdx.x;   // 4 floats each
    float4 v = ((const float4*)x0)[i];
    __half2 h0 = __floats2half2_rn(v.x, v.y);
    __half2 h1 = __floats2half2_rn(v.z, v.w);
    ((uint2*)g_xh)[i] = make_uint2(*(uint32_t*)&h0, *(uint32_t*)&h1);
}

// ---------------- paired fp16 gather: h = x + sum_{j->i} x[j] -------------
// Lanes 0-15 handle even edges, 16-31 odd edges: one LDG.128 fetches 2 rows.
__device__ __forceinline__ void acc_u4(float* a, uint4 p) {
    float2 q;
    q = __half22float2(*(__half2*)&p.x); a[0] += q.x; a[1] += q.y;
    q = __half22float2(*(__half2*)&p.y); a[2] += q.x; a[3] += q.y;
    q = __half22float2(*(__half2*)&p.z); a[4] += q.x; a[5] += q.y;
    q = __half22float2(*(__half2*)&p.w); a[6] += q.x; a[7] += q.y;
}

__global__ void k_agg_h() {
    int w = (int)((blockIdx.x * blockDim.x + threadIdx.x) >> 5);
    int lane = threadIdx.x & 31;
    int half = lane >> 4;            // 0: even edges, 1: odd edges
    int hl = lane & 15;              // 16B chunk within the 256B row
    const uint4* xh4 = (const uint4*)g_xh;   // row = 16 uint4
    int base = g_off[w];
    int end = (w == ROWS - 1) ? EDGES : g_off[w + 1];
    int nE = end - base;
    int nPairEdges = nE & ~1;

    float a[8] = {0.f,0.f,0.f,0.f,0.f,0.f,0.f,0.f};
    // self row contribution: half 0 only (combined once at the end)
    if (half == 0) acc_u4(a, __ldg(xh4 + (size_t)w * 16 + hl));

    for (int j0 = base; j0 < base + nPairEdges; j0 += 32) {
        int avail = min(32, base + nPairEdges - j0);   // even
        int sv = (lane < avail) ? __ldg(&g_adj[j0 + lane]) : 0;
        int mp = avail >> 1;                            // pairs
        int k = 0;
        for (; k + 4 <= mp; k += 4) {                   // 8 rows in flight
            int sA = __shfl_sync(0xffffffffu, sv, 2*k + half);
            int sB = __shfl_sync(0xffffffffu, sv, 2*(k+1) + half);
            int sC = __shfl_sync(0xffffffffu, sv, 2*(k+2) + half);
            int sD = __shfl_sync(0xffffffffu, sv, 2*(k+3) + half);
            uint4 p0 = __ldg(xh4 + (size_t)sA * 16 + hl);
            uint4 p1 = __ldg(xh4 + (size_t)sB * 16 + hl);
            uint4 p2 = __ldg(xh4 + (size_t)sC * 16 + hl);
            uint4 p3 = __ldg(xh4 + (size_t)sD * 16 + hl);
            acc_u4(a, p0); acc_u4(a, p1); acc_u4(a, p2); acc_u4(a, p3);
        }
        for (; k < mp; k++) {
            int sA = __shfl_sync(0xffffffffu, sv, 2*k + half);
            acc_u4(a, __ldg(xh4 + (size_t)sA * 16 + hl));
        }
    }
    if (nE & 1) {   // leftover odd edge: half 0 lanes gather it
        int s = __ldg(&g_adj[end - 1]);
        if (half == 0) acc_u4(a, __ldg(xh4 + (size_t)s * 16 + hl));
    }
    // combine even/odd partials (lane l <-> lane l^16 hold same chunk hl)
    #pragma unroll
    for (int i = 0; i < 8; i++) a[i] += __shfl_xor_sync(0xffffffffu, a[i], 16);

    if (half == 0) {
        __half2 h0 = __floats2half2_rn(a[0], a[1]);
        __half2 h1 = __floats2half2_rn(a[2], a[3]);
        __half2 h2 = __floats2half2_rn(a[4], a[5]);
        __half2 h3 = __floats2half2_rn(a[6], a[7]);
        uint4 o = make_uint4(*(uint32_t*)&h0, *(uint32_t*)&h1,
                             *(uint32_t*)&h2, *(uint32_t*)&h3);
        ((uint4*)g_hh)[(size_t)w * 16 + hl] = o;
    }
}

// ---------------- weight pre-pack (unchanged) -----
__global__ void k_pack(const float* __restrict__ Ws1, const float* __restrict__ Ws2) {
    int idx = blockIdx.x * 256 + threadIdx.x;
    if (idx >= Ln * 8192) return;
    int l = idx / 8192, r = idx % 8192;
    int kt = r >> 10, np = (r >> 7) & 7, lane = (r >> 2) & 31, j = r & 3;
    int g = lane >> 2, tig = lane & 3;
    int nt = np * 2 + (j >> 1);
    int k0 = kt * 16 + tig * 2 + ((j & 1) ? 8 : 0);
    int n = nt * 8 + g;
    const float* W1 = Ws1 + (size_t)l * Dn * Dn;
    const float* W2 = Ws2 + (size_t)l * Dn * Dn;
    __half2 h1 = __halves2half2(__float2half_rn(W1[(size_t)k0 * Dn + n]),
                                __float2half_rn(W1[(size_t)(k0 + 1) * Dn + n]));
    __half2 h2 = __halves2half2(__float2half_rn(W2[(size_t)k0 * Dn + n]),
                                __float2half_rn(W2[(size_t)(k0 + 1) * Dn + n]));
    g_W1h[idx] = *(uint32_t*)&h1;
    g_W2h[idx] = *(uint32_t*)&h2;
}

// ---------------- fused MLP via mma.sync fp16 (warp-private, 2 CTA/SM) ----
#define A_STRIDE_B 272
#define SM_TOT (2048 + 32768 + 32768 + 128*A_STRIDE_B)   // 102400
#define MLP_GRID 296

__global__ void __launch_bounds__(256, 2)
k_mlp_mma(int layer,
          const float* __restrict__ b1, const float* __restrict__ b2,
          const float* __restrict__ lng, const float* __restrict__ lnb,
          int addRes, int writeOut) {
    extern __shared__ float sm[];
    float* b1s  = sm;
    float* b2s  = sm + 128;
    float* lngs = sm + 256;
    float* lnbs = sm + 384;
    uint32_t* wf1 = (uint32_t*)(sm + 512);      // 8192 u32
    uint32_t* wf2 = wf1 + 8192;                 // 8192 u32
    char* Ab = (char*)(wf2 + 8192);             // 128 rows x 272B

    int tid = threadIdx.x;
    int wid = tid >> 5, lane = tid & 31;
    int g = lane >> 2, tig = lane & 3;

    {   // preload weights + vectors
        const uint4* w1g = (const uint4*)(g_W1h + (size_t)layer * 8192);
        const uint4* w2g = (const uint4*)(g_W2h + (size_t)layer * 8192);
        uint4* w1s = (uint4*)wf1;
        uint4* w2s = (uint4*)wf2;
        #pragma unroll 4
        for (int i = tid; i < 2048; i += 256) { w1s[i] = __ldg(w1g + i); w2s[i] = __ldg(w2g + i); }
        if (tid < 128) {
            b1s[tid]  = __ldg(b1 + tid);
            b2s[tid]  = __ldg(b2 + tid);
            lngs[tid] = __ldg(lng + tid);
            lnbs[tid] = __ldg(lnb + tid);
        }
    }
    __syncthreads();

    const uint2* hh = (const uint2*)g_hh;
    const uint32_t* xr = (const uint32_t*)g_xh;   // residual source (fp16)
    uint32_t* xw = (uint32_t*)g_xh;               // next-layer x (fp16)

    char* rp0 = Ab + (wid * 16 + g) * A_STRIDE_B;
    char* rp1 = rp0 + 8 * A_STRIDE_B;

    float acc[16][4];

    for (int tile = blockIdx.x; tile < NT128; tile += MLP_GRID) {
        int rowbase = tile * 128;
        int wrow = rowbase + wid * 16;

        // ---- fill own 16 rows: raw fp16 copy from g_hh
        {
            char* arow = Ab + wid * 16 * A_STRIDE_B;
            #pragma unroll
            for (int i = 0; i < 16; i++) {
                uint2 p = make_uint2(0u, 0u);
                if (wrow + i < ROWS)
                    p = __ldg(hh + (size_t)(wrow + i) * 32 + lane);
                *(uint2*)(arow + i * A_STRIDE_B + lane * 8) = p;
            }
        }
        __syncwarp();

        // ---- GEMM1 (1-deep b-frag prefetch)
        #pragma unroll
        for (int nt = 0; nt < 16; nt++) { acc[nt][0]=acc[nt][1]=acc[nt][2]=acc[nt][3]=0.f; }
        #pragma unroll
        for (int kt = 0; kt < 8; kt++) {
            uint32_t a0 = *(const uint32_t*)(rp0 + kt*32 + tig*4);
            uint32_t a1 = *(const uint32_t*)(rp1 + kt*32 + tig*4);
            uint32_t a2 = *(const uint32_t*)(rp0 + kt*32 + tig*4 + 16);
            uint32_t a3 = *(const uint32_t*)(rp1 + kt*32 + tig*4 + 16);
            const uint4* wfb = (const uint4*)wf1 + kt * 8 * 32 + lane;
            uint4 bcur = wfb[0];
            #pragma unroll
            for (int np = 0; np < 8; np++) {
                uint4 bnext;
                if (np < 7) bnext = wfb[(np + 1) * 32];
                mma_f16(acc[2*np],   a0, a1, a2, a3, bcur.x, bcur.y);
                mma_f16(acc[2*np+1], a0, a1, a2, a3, bcur.z, bcur.w);
                if (np < 7) bcur = bnext;
            }
        }

        // ---- relu(+b1) -> fp16, stage back into own A rows
        __syncwarp();
        #pragma unroll
        for (int nt = 0; nt < 16; nt++) {
            float2 bb = *(float2*)&b1s[nt*8 + tig*2];
            __half2 lo = __floats2half2_rn(fmaxf(acc[nt][0] + bb.x, 0.f),
                                           fmaxf(acc[nt][1] + bb.y, 0.f));
            __half2 hi = __floats2half2_rn(fmaxf(acc[nt][2] + bb.x, 0.f),
                                           fmaxf(acc[nt][3] + bb.y, 0.f));
            *(uint32_t*)(rp0 + nt*16 + tig*4) = *(uint32_t*)&lo;
            *(uint32_t*)(rp1 + nt*16 + tig*4) = *(uint32_t*)&hi;
        }
        __syncwarp();

        // ---- GEMM2 (1-deep b-frag prefetch)
        #pragma unroll
        for (int nt = 0; nt < 16; nt++) { acc[nt][0]=acc[nt][1]=acc[nt][2]=acc[nt][3]=0.f; }
        #pragma unroll
        for (int kt = 0; kt < 8; kt++) {
            uint32_t a0 = *(const uint32_t*)(rp0 + kt*32 + tig*4);
            uint32_t a1 = *(const uint32_t*)(rp1 + kt*32 + tig*4);
            uint32_t a2 = *(const uint32_t*)(rp0 + kt*32 + tig*4 + 16);
            uint32_t a3 = *(const uint32_t*)(rp1 + kt*32 + tig*4 + 16);
            const uint4* wfb = (const uint4*)wf2 + kt * 8 * 32 + lane;
            uint4 bcur = wfb[0];
            #pragma unroll
            for (int np = 0; np < 8; np++) {
                uint4 bnext;
                if (np < 7) bnext = wfb[(np + 1) * 32];
                mma_f16(acc[2*np],   a0, a1, a2, a3, bcur.x, bcur.y);
                mma_f16(acc[2*np+1], a0, a1, a2, a3, bcur.z, bcur.w);
                if (np < 7) bcur = bnext;
            }
        }

        // ---- epilogue: +b2 (+fp16 residual), LN over quad, store
        {
            int r0g = wrow + g, r1g = wrow + g + 8;
            bool v0 = r0g < ROWS, v1 = r1g < ROWS;
            float s0 = 0.f, ss0 = 0.f, s1 = 0.f, ss1 = 0.f;
            #pragma unroll
            for (int nt = 0; nt < 16; nt++) {
                int c = nt*8 + tig*2;
                float2 bb = *(float2*)&b2s[c];
                acc[nt][0] += bb.x; acc[nt][1] += bb.y;
                acc[nt][2] += bb.x; acc[nt][3] += bb.y;
                if (addRes) {
                    if (v0) {
                        uint32_t rv = __ldg(xr + (((size_t)r0g * Dn + c) >> 1));
                        float2 q = __half22float2(*(__half2*)&rv);
                        acc[nt][0] += q.x; acc[nt][1] += q.y;
                    }
                    if (v1) {
                        uint32_t rv = __ldg(xr + (((size_t)r1g * Dn + c) >> 1));
                        float2 q = __half22float2(*(__half2*)&rv);
                        acc[nt][2] += q.x; acc[nt][3] += q.y;
                    }
                }
                s0  += acc[nt][0] + acc[nt][1];
                ss0 += acc[nt][0]*acc[nt][0] + acc[nt][1]*acc[nt][1];
                s1  += acc[nt][2] + acc[nt][3];
                ss1 += acc[nt][2]*acc[nt][2] + acc[nt][3]*acc[nt][3];
            }
            s0  += __shfl_xor_sync(0xffffffffu, s0, 1);  s0  += __shfl_xor_sync(0xffffffffu, s0, 2);
            ss0 += __shfl_xor_sync(0xffffffffu, ss0, 1); ss0 += __shfl_xor_sync(0xffffffffu, ss0, 2);
            s1  += __shfl_xor_sync(0xffffffffu, s1, 1);  s1  += __shfl_xor_sync(0xffffffffu, s1, 2);
            ss1 += __shfl_xor_sync(0xffffffffu, ss1, 1); ss1 += __shfl_xor_sync(0xffffffffu, ss1, 2);
            float mu0 = s0 * (1.f/128.f), mu1 = s1 * (1.f/128.f);
            float iv0 = rsqrtf(ss0 * (1.f/128.f) - mu0*mu0 + LN_EPS);
            float iv1 = rsqrtf(ss1 * (1.f/128.f) - mu1*mu1 + LN_EPS);
            #pragma unroll
            for (int nt = 0; nt < 16; nt++) {
                int c = nt*8 + tig*2;
                float2 gg = *(float2*)&lngs[c];
                float2 bb = *(float2*)&lnbs[c];
                if (v0) {
                    float2 ov;
                    ov.x = (acc[nt][0] - mu0) * iv0 * gg.x + bb.x;
                    ov.y = (acc[nt][1] - mu0) * iv0 * gg.y + bb.y;
                    if (writeOut) {
                        *(float2*)(g_bufA + (size_t)r0g * Dn + c) = ov;
                    } else {
                        __half2 hv = __floats2half2_rn(ov.x, ov.y);
                        xw[((size_t)r0g * Dn + c) >> 1] = *(uint32_t*)&hv;
                    }
                }
                if (v1) {
                    float2 ov;
                    ov.x = (acc[nt][2] - mu1) * iv1 * gg.x + bb.x;
                    ov.y = (acc[nt][3] - mu1) * iv1 * gg.y + bb.y;
                    if (writeOut) {
                        *(float2*)(g_bufA + (size_t)r1g * Dn + c) = ov;
                    } else {
                        __half2 hv = __floats2half2_rn(ov.x, ov.y);
                        xw[((size_t)r1g * Dn + c) >> 1] = *(uint32_t*)&hv;
                    }
                }
            }
        }
        __syncwarp();
    }
}

// ---------------- readout + attention (unchanged) ----------------
__global__ void k_zero() { g_gvec[threadIdx.x] = 0.f; }

__global__ void k_readout() {
    const float* x = g_bufA;
    int g = blockIdx.x;
    int chunk = blockIdx.y;
    int d = threadIdx.x;
    int i0 = chunk * 1563;
    int i1 = min(Nn, i0 + 1563);
    float s = 0.f;
    const float* base = x + (size_t)g * Nn * Dn + d;
    for (int i = i0; i < i1; i++) s += __ldg(base + (size_t)i * Dn);
    atomicAdd(&g_gvec[g * Dn + d], s);
}

__global__ void k_att(const float* __restrict__ w1, const float* __restrict__ w2,
                      float* __restrict__ out) {
    __shared__ float gm[Gn * Dn];
    __shared__ float sup[AHn * Gn];
    __shared__ float att[NEx * Gn];
    int tid = threadIdx.x;
    for (int i = tid; i < Gn * Dn; i += 256) gm[i] = g_gvec[i];
    __syncthreads();
    if (tid < AHn * Gn) {
        int ah = tid >> 2, gr = tid & 3;
        float s = 0.f;
        #pragma unroll 8
        for (int d = 0; d < Dn; d++) s = fmaf(__ldg(w1 + ah * Dn + d), gm[gr * Dn + d], s);
        sup[tid] = tanhf(s);
    }
    __syncthreads();
    if (tid < NEx * Gn) {
        int e = tid >> 2, gr = tid & 3;
        float s = 0.f;
        #pragma unroll 8
        for (int a = 0; a < AHn; a++) s = fmaf(__ldg(w2 + e * AHn + a), sup[a * 4 + gr], s);
        att[tid] = s;
    }
    __syncthreads();
    if (tid < NEx) {
        float m = -1e30f;
        #pragma unroll
        for (int gr = 0; gr < 4; gr++) m = fmaxf(m, att[tid * 4 + gr]);
        float ex[4]; float sum = 0.f;
        #pragma unroll
        for (int gr = 0; gr < 4; gr++) { ex[gr] = expf(att[tid * 4 + gr] - m); sum += ex[gr]; }
        float inv = 1.f / sum;
        #pragma unroll
        for (int gr = 0; gr < 4; gr++) att[tid * 4 + gr] = ex[gr] * inv;
    }
    __syncthreads();
    for (int o = tid; o < NEx * Dn; o += 256) {
        int e = o >> 7, d = o & 127;
        float s = 0.f;
        #pragma unroll
        for (int gr = 0; gr < 4; gr++) s = fmaf(att[e * 4 + gr], gm[gr * Dn + d], s);
        out[o] = s;
    }
}

// ---------------------------------------------------------------------------
extern "C" void kernel_launch(void* const* d_in, const int* in_sizes, int n_in,
                              void* d_out, int out_size) {
    const float* x0  = (const float*)d_in[0];
    const int*   ei  = (const int*)d_in[1];
    const float* Ws1 = (const float*)d_in[3];
    const float* bs1 = (const float*)d_in[4];
    const float* Ws2 = (const float*)d_in[5];
    const float* bs2 = (const float*)d_in[6];
    const float* lng = (const float*)d_in[7];
    const float* lnb = (const float*)d_in[8];
    const float* aw1 = (const float*)d_in[9];
    const float* aw2 = (const float*)d_in[10];
    float* out = (float*)d_out;

    cudaFuncSetAttribute(k_mlp_mma, cudaFuncAttributeMaxDynamicSharedMemorySize, SM_TOT);

    k_pack<<<(Ln * 8192 + 255) / 256, 256>>>(Ws1, Ws2);

    // CSR build (once per launch; edge index is constant input)
    k_csr_zero<<<NB_SCAN, 256>>>();
    k_csr_count<<<EDGES / 256, 256>>>(ei);
    k_scan_block<<<NB_SCAN, 256>>>();
    k_scan_top<<<1, 1024>>>();
    k_scan_add<<<NB_SCAN, 256>>>();
    k_csr_fill<<<EDGES / 256, 256>>>(ei);

    // fp16 image of the input features
    k_tohalf<<<(ROWS * Dn / 4) / 256, 256>>>(x0);

    for (int l = 0; l < Ln; l++) {
        k_agg_h<<<ROWS / 8, 256>>>();
        k_mlp_mma<<<MLP_GRID, 256, SM_TOT>>>(l,
                                             bs1 + l * Dn, bs2 + l * Dn,
                                             lng + l * Dn, lnb + l * Dn,
                                             (l < Ln - 1) ? 1 : 0,
                                             (l == Ln - 1) ? 1 : 0);
    }
    k_zero<<<1, Gn * Dn>>>();
    k_readout<<<dim3(Gn, 32), Dn>>>();
    k_att<<<1, 256>>>(aw1, aw2, out);
}

// round 12
// speedup vs baseline: 1.0029x; 1.0029x over previous
#include <cuda_runtime.h>
#include <cuda_fp16.h>
#include <cstdint>

#define Gn 4
#define Nn 50000
#define En 400000
#define Dn 128
#define Ln 3
#define NEx 8
#define AHn 64
#define ROWS (Gn*Nn)
#define EDGES (Gn*En)
#define NT128 ((ROWS + 127) / 128)
#define LN_EPS 1e-5f
#define NB_SCAN 782              // ceil(ROWS/256)

// ---------------- scratch (static, allocation-free) ----------------
__device__ float g_bufA[(size_t)ROWS * Dn];   // fp32 final-layer output (readout)
__device__ __half g_xh[(size_t)ROWS * Dn];    // fp16 current-layer features
__device__ __half g_hh[(size_t)ROWS * Dn];    // fp16 h = x + agg
__device__ float g_gvec[Gn * Dn];
__device__ uint32_t g_W1h[Ln * 8192];
__device__ uint32_t g_W2h[Ln * 8192];
// CSR scratch
__device__ int g_cnt[ROWS];
__device__ int g_off[ROWS];
__device__ int g_cur[ROWS];
__device__ int g_adj[EDGES];
__device__ int g_bsum[NB_SCAN];

__device__ __forceinline__ void mma_f16(float* c, uint32_t a0, uint32_t a1,
                                        uint32_t a2, uint32_t a3,
                                        uint32_t b0, uint32_t b1) {
    asm volatile(
        "mma.sync.aligned.m16n8k16.row.col.f32.f16.f16.f32 "
        "{%0,%1,%2,%3}, {%4,%5,%6,%7}, {%8,%9}, {%0,%1,%2,%3};"
        : "+f"(c[0]), "+f"(c[1]), "+f"(c[2]), "+f"(c[3])
        : "r"(a0), "r"(a1), "r"(a2), "r"(a3), "r"(b0), "r"(b1));
}

// ---------------- CSR build (unchanged) ----------------
__global__ void k_csr_zero() {
    int i = blockIdx.x * 256 + threadIdx.x;
    if (i < ROWS) g_cnt[i] = 0;
}
__global__ void k_csr_count(const int* __restrict__ ei) {
    int t = blockIdx.x * 256 + threadIdx.x;
    int g = t / En, e = t - g * En;
    int dst = ei[(size_t)g * 2 * En + En + e];
    atomicAdd(&g_cnt[g * Nn + dst], 1);
}
__global__ void k_scan_block() {
    __shared__ int s[256];
    int i = blockIdx.x * 256 + threadIdx.x;
    int v = (i < ROWS) ? g_cnt[i] : 0;
    s[threadIdx.x] = v;
    __syncthreads();
    #pragma unroll
    for (int o = 1; o < 256; o <<= 1) {
        int t = (threadIdx.x >= o) ? s[threadIdx.x - o] : 0;
        __syncthreads();
        s[threadIdx.x] += t;
        __syncthreads();
    }
    if (i < ROWS) g_off[i] = s[threadIdx.x] - v;
    if (threadIdx.x == 255) g_bsum[blockIdx.x] = s[255];
}
__global__ void k_scan_top() {
    __shared__ int s[1024];
    int tid = threadIdx.x;
    int v = (tid < NB_SCAN) ? g_bsum[tid] : 0;
    s[tid] = v;
    __syncthreads();
    #pragma unroll
    for (int o = 1; o < 1024; o <<= 1) {
        int t = (tid >= o) ? s[tid - o] : 0;
        __syncthreads();
        s[tid] += t;
        __syncthreads();
    }
    if (tid < NB_SCAN) g_bsum[tid] = s[tid] - v;
}
__global__ void k_scan_add() {
    int i = blockIdx.x * 256 + threadIdx.x;
    if (i < ROWS) {
        int o = g_off[i] + g_bsum[blockIdx.x];
        g_off[i] = o;
        g_cur[i] = o;
    }
}
__global__ void k_csr_fill(const int* __restrict__ ei) {
    int t = blockIdx.x * 256 + threadIdx.x;
    int g = t / En, e = t - g * En;
    const int* eig = ei + (size_t)g * 2 * En;
    int src = eig[e];
    int dst = eig[En + e];
    int pos = atomicAdd(&g_cur[g * Nn + dst], 1);
    g_adj[pos] = g * Nn + src;
}

// ---------------- fp16 conversion of the input features ----------------
__global__ void k_tohalf(const float* __restrict__ x0) {
    size_t i = (size_t)blockIdx.x * 256 + threadIdx.x;   // 4 floats each
    float4 v = ((const float4*)x0)[i];
    __half2 h0 = __floats2half2_rn(v.x, v.y);
    __half2 h1 = __floats2half2_rn(v.z, v.w);
    ((uint2*)g_xh)[i] = make_uint2(*(uint32_t*)&h0, *(uint32_t*)&h1);
}

// ---------------- paired fp16 gather: h = x + sum_{j->i} x[j] -------------
// Lanes 0-15 handle even edges, 16-31 odd edges: one LDG.128 fetches 2 rows.
__device__ __forceinline__ void acc_u4(float* a, uint4 p) {
    float2 q;
    q = __half22float2(*(__half2*)&p.x); a[0] += q.x; a[1] += q.y;
    q = __half22float2(*(__half2*)&p.y); a[2] += q.x; a[3] += q.y;
    q = __half22float2(*(__half2*)&p.z); a[4] += q.x; a[5] += q.y;
    q = __half22float2(*(__half2*)&p.w); a[6] += q.x; a[7] += q.y;
}

__global__ void k_agg_h() {
    int w = (int)((blockIdx.x * blockDim.x + threadIdx.x) >> 5);
    int lane = threadIdx.x & 31;
    int half = lane >> 4;            // 0: even edges, 1: odd edges
    int hl = lane & 15;              // 16B chunk within the 256B row
    const uint4* xh4 = (const uint4*)g_xh;   // row = 16 uint4
    int base = g_off[w];
    int end = (w == ROWS - 1) ? EDGES : g_off[w + 1];
    int nE = end - base;
    int nPairEdges = nE & ~1;

    float a[8] = {0.f,0.f,0.f,0.f,0.f,0.f,0.f,0.f};
    // self row contribution: half 0 only (combined once at the end)
    if (half == 0) acc_u4(a, __ldg(xh4 + (size_t)w * 16 + hl));

    for (int j0 = base; j0 < base + nPairEdges; j0 += 32) {
        int avail = min(32, base + nPairEdges - j0);   // even
        int sv = (lane < avail) ? __ldg(&g_adj[j0 + lane]) : 0;
        int mp = avail >> 1;                            // pairs
        int k = 0;
        for (; k + 4 <= mp; k += 4) {                   // 8 rows in flight
            int sA = __shfl_sync(0xffffffffu, sv, 2*k + half);
            int sB = __shfl_sync(0xffffffffu, sv, 2*(k+1) + half);
            int sC = __shfl_sync(0xffffffffu, sv, 2*(k+2) + half);
            int sD = __shfl_sync(0xffffffffu, sv, 2*(k+3) + half);
            uint4 p0 = __ldg(xh4 + (size_t)sA * 16 + hl);
            uint4 p1 = __ldg(xh4 + (size_t)sB * 16 + hl);
            uint4 p2 = __ldg(xh4 + (size_t)sC * 16 + hl);
            uint4 p3 = __ldg(xh4 + (size_t)sD * 16 + hl);
            acc_u4(a, p0); acc_u4(a, p1); acc_u4(a, p2); acc_u4(a, p3);
        }
        for (; k < mp; k++) {
            int sA = __shfl_sync(0xffffffffu, sv, 2*k + half);
            acc_u4(a, __ldg(xh4 + (size_t)sA * 16 + hl));
        }
    }
    if (nE & 1) {   // leftover odd edge: half 0 lanes gather it
        int s = __ldg(&g_adj[end - 1]);
        if (half == 0) acc_u4(a, __ldg(xh4 + (size_t)s * 16 + hl));
    }
    // combine even/odd partials (lane l <-> lane l^16 hold same chunk hl)
    #pragma unroll
    for (int i = 0; i < 8; i++) a[i] += __shfl_xor_sync(0xffffffffu, a[i], 16);

    if (half == 0) {
        __half2 h0 = __floats2half2_rn(a[0], a[1]);
        __half2 h1 = __floats2half2_rn(a[2], a[3]);
        __half2 h2 = __floats2half2_rn(a[4], a[5]);
        __half2 h3 = __floats2half2_rn(a[6], a[7]);
        uint4 o = make_uint4(*(uint32_t*)&h0, *(uint32_t*)&h1,
                             *(uint32_t*)&h2, *(uint32_t*)&h3);
        ((uint4*)g_hh)[(size_t)w * 16 + hl] = o;
    }
}

// ---------------- weight pre-pack (unchanged) -----
__global__ void k_pack(const float* __restrict__ Ws1, const float* __restrict__ Ws2) {
    int idx = blockIdx.x * 256 + threadIdx.x;
    if (idx >= Ln * 8192) return;
    int l = idx / 8192, r = idx % 8192;
    int kt = r >> 10, np = (r >> 7) & 7, lane = (r >> 2) & 31, j = r & 3;
    int g = lane >> 2, tig = lane & 3;
    int nt = np * 2 + (j >> 1);
    int k0 = kt * 16 + tig * 2 + ((j & 1) ? 8 : 0);
    int n = nt * 8 + g;
    const float* W1 = Ws1 + (size_t)l * Dn * Dn;
    const float* W2 = Ws2 + (size_t)l * Dn * Dn;
    __half2 h1 = __halves2half2(__float2half_rn(W1[(size_t)k0 * Dn + n]),
                                __float2half_rn(W1[(size_t)(k0 + 1) * Dn + n]));
    __half2 h2 = __halves2half2(__float2half_rn(W2[(size_t)k0 * Dn + n]),
                                __float2half_rn(W2[(size_t)(k0 + 1) * Dn + n]));
    g_W1h[idx] = *(uint32_t*)&h1;
    g_W2h[idx] = *(uint32_t*)&h2;
}

// ---------------- fused MLP via mma.sync fp16 (exact R10 version, no prefetch) ----
#define A_STRIDE_B 272
#define SM_TOT (2048 + 32768 + 32768 + 128*A_STRIDE_B)   // 102400
#define MLP_GRID 296

__global__ void __launch_bounds__(256, 2)
k_mlp_mma(int layer,
          const float* __restrict__ b1, const float* __restrict__ b2,
          const float* __restrict__ lng, const float* __restrict__ lnb,
          int addRes, int writeOut) {
    extern __shared__ float sm[];
    float* b1s  = sm;
    float* b2s  = sm + 128;
    float* lngs = sm + 256;
    float* lnbs = sm + 384;
    uint32_t* wf1 = (uint32_t*)(sm + 512);      // 8192 u32
    uint32_t* wf2 = wf1 + 8192;                 // 8192 u32
    char* Ab = (char*)(wf2 + 8192);             // 128 rows x 272B

    int tid = threadIdx.x;
    int wid = tid >> 5, lane = tid & 31;
    int g = lane >> 2, tig = lane & 3;

    {   // preload weights + vectors
        const uint4* w1g = (const uint4*)(g_W1h + (size_t)layer * 8192);
        const uint4* w2g = (const uint4*)(g_W2h + (size_t)layer * 8192);
        uint4* w1s = (uint4*)wf1;
        uint4* w2s = (uint4*)wf2;
        #pragma unroll 4
        for (int i = tid; i < 2048; i += 256) { w1s[i] = __ldg(w1g + i); w2s[i] = __ldg(w2g + i); }
        if (tid < 128) {
            b1s[tid]  = __ldg(b1 + tid);
            b2s[tid]  = __ldg(b2 + tid);
            lngs[tid] = __ldg(lng + tid);
            lnbs[tid] = __ldg(lnb + tid);
        }
    }
    __syncthreads();

    const uint2* hh = (const uint2*)g_hh;
    const uint32_t* xr = (const uint32_t*)g_xh;   // residual source (fp16)
    uint32_t* xw = (uint32_t*)g_xh;               // next-layer x (fp16)

    char* rp0 = Ab + (wid * 16 + g) * A_STRIDE_B;
    char* rp1 = rp0 + 8 * A_STRIDE_B;

    float acc[16][4];

    for (int tile = blockIdx.x; tile < NT128; tile += MLP_GRID) {
        int rowbase = tile * 128;
        int wrow = rowbase + wid * 16;

        // ---- fill own 16 rows: raw fp16 copy from g_hh
        {
            char* arow = Ab + wid * 16 * A_STRIDE_B;
            #pragma unroll
            for (int i = 0; i < 16; i++) {
                uint2 p = make_uint2(0u, 0u);
                if (wrow + i < ROWS)
                    p = __ldg(hh + (size_t)(wrow + i) * 32 + lane);
                *(uint2*)(arow + i * A_STRIDE_B + lane * 8) = p;
            }
        }
        __syncwarp();

        // ---- GEMM1
        #pragma unroll
        for (int nt = 0; nt < 16; nt++) { acc[nt][0]=acc[nt][1]=acc[nt][2]=acc[nt][3]=0.f; }
        #pragma unroll
        for (int kt = 0; kt < 8; kt++) {
            uint32_t a0 = *(const uint32_t*)(rp0 + kt*32 + tig*4);
            uint32_t a1 = *(const uint32_t*)(rp1 + kt*32 + tig*4);
            uint32_t a2 = *(const uint32_t*)(rp0 + kt*32 + tig*4 + 16);
            uint32_t a3 = *(const uint32_t*)(rp1 + kt*32 + tig*4 + 16);
            const uint4* wfb = (const uint4*)wf1 + kt * 8 * 32 + lane;
            #pragma unroll
            for (int np = 0; np < 8; np++) {
                uint4 b = wfb[np * 32];
                mma_f16(acc[2*np],   a0, a1, a2, a3, b.x, b.y);
                mma_f16(acc[2*np+1], a0, a1, a2, a3, b.z, b.w);
            }
        }

        // ---- relu(+b1) -> fp16, stage back into own A rows
        __syncwarp();
        #pragma unroll
        for (int nt = 0; nt < 16; nt++) {
            float2 bb = *(float2*)&b1s[nt*8 + tig*2];
            __half2 lo = __floats2half2_rn(fmaxf(acc[nt][0] + bb.x, 0.f),
                                           fmaxf(acc[nt][1] + bb.y, 0.f));
            __half2 hi = __floats2half2_rn(fmaxf(acc[nt][2] + bb.x, 0.f),
                                           fmaxf(acc[nt][3] + bb.y, 0.f));
            *(uint32_t*)(rp0 + nt*16 + tig*4) = *(uint32_t*)&lo;
            *(uint32_t*)(rp1 + nt*16 + tig*4) = *(uint32_t*)&hi;
        }
        __syncwarp();

        // ---- GEMM2
        #pragma unroll
        for (int nt = 0; nt < 16; nt++) { acc[nt][0]=acc[nt][1]=acc[nt][2]=acc[nt][3]=0.f; }
        #pragma unroll
        for (int kt = 0; kt < 8; kt++) {
            uint32_t a0 = *(const uint32_t*)(rp0 + kt*32 + tig*4);
            uint32_t a1 = *(const uint32_t*)(rp1 + kt*32 + tig*4);
            uint32_t a2 = *(const uint32_t*)(rp0 + kt*32 + tig*4 + 16);
            uint32_t a3 = *(const uint32_t*)(rp1 + kt*32 + tig*4 + 16);
            const uint4* wfb = (const uint4*)wf2 + kt * 8 * 32 + lane;
            #pragma unroll
            for (int np = 0; np < 8; np++) {
                uint4 b = wfb[np * 32];
                mma_f16(acc[2*np],   a0, a1, a2, a3, b.x, b.y);
                mma_f16(acc[2*np+1], a0, a1, a2, a3, b.z, b.w);
            }
        }

        // ---- epilogue: +b2 (+fp16 residual), LN over quad, store
        {
            int r0g = wrow + g, r1g = wrow + g + 8;
            bool v0 = r0g < ROWS, v1 = r1g < ROWS;
            float s0 = 0.f, ss0 = 0.f, s1 = 0.f, ss1 = 0.f;
            #pragma unroll
            for (int nt = 0; nt < 16; nt++) {
                int c = nt*8 + tig*2;
                float2 bb = *(float2*)&b2s[c];
                acc[nt][0] += bb.x; acc[nt][1] += bb.y;
                acc[nt][2] += bb.x; acc[nt][3] += bb.y;
                if (addRes) {
                    if (v0) {
                        uint32_t rv = __ldg(xr + (((size_t)r0g * Dn + c) >> 1));
                        float2 q = __half22float2(*(__half2*)&rv);
                        acc[nt][0] += q.x; acc[nt][1] += q.y;
                    }
                    if (v1) {
                        uint32_t rv = __ldg(xr + (((size_t)r1g * Dn + c) >> 1));
                        float2 q = __half22float2(*(__half2*)&rv);
                        acc[nt][2] += q.x; acc[nt][3] += q.y;
                    }
                }
                s0  += acc[nt][0] + acc[nt][1];
                ss0 += acc[nt][0]*acc[nt][0] + acc[nt][1]*acc[nt][1];
                s1  += acc[nt][2] + acc[nt][3];
                ss1 += acc[nt][2]*acc[nt][2] + acc[nt][3]*acc[nt][3];
            }
            s0  += __shfl_xor_sync(0xffffffffu, s0, 1);  s0  += __shfl_xor_sync(0xffffffffu, s0, 2);
            ss0 += __shfl_xor_sync(0xffffffffu, ss0, 1); ss0 += __shfl_xor_sync(0xffffffffu, ss0, 2);
            s1  += __shfl_xor_sync(0xffffffffu, s1, 1);  s1  += __shfl_xor_sync(0xffffffffu, s1, 2);
            ss1 += __shfl_xor_sync(0xffffffffu, ss1, 1); ss1 += __shfl_xor_sync(0xffffffffu, ss1, 2);
            float mu0 = s0 * (1.f/128.f), mu1 = s1 * (1.f/128.f);
            float iv0 = rsqrtf(ss0 * (1.f/128.f) - mu0*mu0 + LN_EPS);
            float iv1 = rsqrtf(ss1 * (1.f/128.f) - mu1*mu1 + LN_EPS);
            #pragma unroll
            for (int nt = 0; nt < 16; nt++) {
                int c = nt*8 + tig*2;
                float2 gg = *(float2*)&lngs[c];
                float2 bb = *(float2*)&lnbs[c];
                if (v0) {
                    float2 ov;
                    ov.x = (acc[nt][0] - mu0) * iv0 * gg.x + bb.x;
                    ov.y = (acc[nt][1] - mu0) * iv0 * gg.y + bb.y;
                    if (writeOut) {
                        *(float2*)(g_bufA + (size_t)r0g * Dn + c) = ov;
                    } else {
                        __half2 hv = __floats2half2_rn(ov.x, ov.y);
                        xw[((size_t)r0g * Dn + c) >> 1] = *(uint32_t*)&hv;
                    }
                }
                if (v1) {
                    float2 ov;
                    ov.x = (acc[nt][2] - mu1) * iv1 * gg.x + bb.x;
                    ov.y = (acc[nt][3] - mu1) * iv1 * gg.y + bb.y;
                    if (writeOut) {
                        *(float2*)(g_bufA + (size_t)r1g * Dn + c) = ov;
                    } else {
                        __half2 hv = __floats2half2_rn(ov.x, ov.y);
                        xw[((size_t)r1g * Dn + c) >> 1] = *(uint32_t*)&hv;
                    }
                }
            }
        }
        __syncwarp();
    }
}

// ---------------- readout + attention (unchanged) ----------------
__global__ void k_zero() { g_gvec[threadIdx.x] = 0.f; }

__global__ void k_readout() {
    const float* x = g_bufA;
    int g = blockIdx.x;
    int chunk = blockIdx.y;
    int d = threadIdx.x;
    int i0 = chunk * 1563;
    int i1 = min(Nn, i0 + 1563);
    float s = 0.f;
    const float* base = x + (size_t)g * Nn * Dn + d;
    for (int i = i0; i < i1; i++) s += __ldg(base + (size_t)i * Dn);
    atomicAdd(&g_gvec[g * Dn + d], s);
}

__global__ void k_att(const float* __restrict__ w1, const float* __restrict__ w2,
                      float* __restrict__ out) {
    __shared__ float gm[Gn * Dn];
    __shared__ float sup[AHn * Gn];
    __shared__ float att[NEx * Gn];
    int tid = threadIdx.x;
    for (int i = tid; i < Gn * Dn; i += 256) gm[i] = g_gvec[i];
    __syncthreads();
    if (tid < AHn * Gn) {
        int ah = tid >> 2, gr = tid & 3;
        float s = 0.f;
        #pragma unroll 8
        for (int d = 0; d < Dn; d++) s = fmaf(__ldg(w1 + ah * Dn + d), gm[gr * Dn + d], s);
        sup[tid] = tanhf(s);
    }
    __syncthreads();
    if (tid < NEx * Gn) {
        int e = tid >> 2, gr = tid & 3;
        float s = 0.f;
        #pragma unroll 8
        for (int a = 0; a < AHn; a++) s = fmaf(__ldg(w2 + e * AHn + a), sup[a * 4 + gr], s);
        att[tid] = s;
    }
    __syncthreads();
    if (tid < NEx) {
        float m = -1e30f;
        #pragma unroll
        for (int gr = 0; gr < 4; gr++) m = fmaxf(m, att[tid * 4 + gr]);
        float ex[4]; float sum = 0.f;
        #pragma unroll
        for (int gr = 0; gr < 4; gr++) { ex[gr] = expf(att[tid * 4 + gr] - m); sum += ex[gr]; }
        float inv = 1.f / sum;
        #pragma unroll
        for (int gr = 0; gr < 4; gr++) att[tid * 4 + gr] = ex[gr] * inv;
    }
    __syncthreads();
    for (int o = tid; o < NEx * Dn; o += 256) {
        int e = o >> 7, d = o & 127;
        float s = 0.f;
        #pragma unroll
        for (int gr = 0; gr < 4; gr++) s = fmaf(att[e * 4 + gr], gm[gr * Dn + d], s);
        out[o] = s;
    }
}

// ---------------------------------------------------------------------------
extern "C" void kernel_launch(void* const* d_in, const int* in_sizes, int n_in,
                              void* d_out, int out_size) {
    const float* x0  = (const float*)d_in[0];
    const int*   ei  = (const int*)d_in[1];
    const float* Ws1 = (const float*)d_in[3];
    const float* bs1 = (const float*)d_in[4];
    const float* Ws2 = (const float*)d_in[5];
    const float* bs2 = (const float*)d_in[6];
    const float* lng = (const float*)d_in[7];
    const float* lnb = (const float*)d_in[8];
    const float* aw1 = (const float*)d_in[9];
    const float* aw2 = (const float*)d_in[10];
    float* out = (float*)d_out;

    cudaFuncSetAttribute(k_mlp_mma, cudaFuncAttributeMaxDynamicSharedMemorySize, SM_TOT);

    k_pack<<<(Ln * 8192 + 255) / 256, 256>>>(Ws1, Ws2);

    // CSR build (once per launch; edge index is constant input)
    k_csr_zero<<<NB_SCAN, 256>>>();
    k_csr_count<<<EDGES / 256, 256>>>(ei);
    k_scan_block<<<NB_SCAN, 256>>>();
    k_scan_top<<<1, 1024>>>();
    k_scan_add<<<NB_SCAN, 256>>>();
    k_csr_fill<<<EDGES / 256, 256>>>(ei);

    // fp16 image of the input features
    k_tohalf<<<(ROWS * Dn / 4) / 256, 256>>>(x0);

    for (int l = 0; l < Ln; l++) {
        k_agg_h<<<ROWS / 8, 256>>>();
        k_mlp_mma<<<MLP_GRID, 256, SM_TOT>>>(l,
                                             bs1 + l * Dn, bs2 + l * Dn,
                                             lng + l * Dn, lnb + l * Dn,
                                             (l < Ln - 1) ? 1 : 0,
                                             (l == Ln - 1) ? 1 : 0);
    }
    k_zero<<<1, Gn * Dn>>>();
    k_readout<<<dim3(Gn, 32), Dn>>>();
    k_att<<<1, 256>>>(aw1, aw2, out);
}

// round 13
// speedup vs baseline: 1.0838x; 1.0807x over previous
#include <cuda_runtime.h>
#include <cuda_fp16.h>
#include <cstdint>

#define Gn 4
#define Nn 50000
#define En 400000
#define Dn 128
#define Ln 3
#define NEx 8
#define AHn 64
#define ROWS (Gn*Nn)
#define EDGES (Gn*En)
#define NT128 ((ROWS + 127) / 128)
#define LN_EPS 1e-5f
#define NB_SCAN 782              // ceil(ROWS/256)

// ---------------- scratch (static, allocation-free) ----------------
__device__ __half g_xh[(size_t)ROWS * Dn];    // fp16 current-layer features
__device__ __half g_hh[(size_t)ROWS * Dn];    // fp16 h = x + agg
__device__ float g_gvec[Gn * Dn];
__device__ uint32_t g_W1h[Ln * 8192];
__device__ uint32_t g_W2h[Ln * 8192];
// CSR scratch
__device__ int g_cnt[ROWS];
__device__ int g_off[ROWS];
__device__ int g_cur[ROWS];
__device__ int g_adj[EDGES];
__device__ int g_bsum[NB_SCAN];

__device__ __forceinline__ void mma_f16(float* c, uint32_t a0, uint32_t a1,
                                        uint32_t a2, uint32_t a3,
                                        uint32_t b0, uint32_t b1) {
    asm volatile(
        "mma.sync.aligned.m16n8k16.row.col.f32.f16.f16.f32 "
        "{%0,%1,%2,%3}, {%4,%5,%6,%7}, {%8,%9}, {%0,%1,%2,%3};"
        : "+f"(c[0]), "+f"(c[1]), "+f"(c[2]), "+f"(c[3])
        : "r"(a0), "r"(a1), "r"(a2), "r"(a3), "r"(b0), "r"(b1));
}

// ---------------- CSR build (unchanged) ----------------
__global__ void k_csr_zero() {
    int i = blockIdx.x * 256 + threadIdx.x;
    if (i < ROWS) g_cnt[i] = 0;
}
__global__ void k_csr_count(const int* __restrict__ ei) {
    int t = blockIdx.x * 256 + threadIdx.x;
    int g = t / En, e = t - g * En;
    int dst = ei[(size_t)g * 2 * En + En + e];
    atomicAdd(&g_cnt[g * Nn + dst], 1);
}
__global__ void k_scan_block() {
    __shared__ int s[256];
    int i = blockIdx.x * 256 + threadIdx.x;
    int v = (i < ROWS) ? g_cnt[i] : 0;
    s[threadIdx.x] = v;
    __syncthreads();
    #pragma unroll
    for (int o = 1; o < 256; o <<= 1) {
        int t = (threadIdx.x >= o) ? s[threadIdx.x - o] : 0;
        __syncthreads();
        s[threadIdx.x] += t;
        __syncthreads();
    }
    if (i < ROWS) g_off[i] = s[threadIdx.x] - v;
    if (threadIdx.x == 255) g_bsum[blockIdx.x] = s[255];
}
__global__ void k_scan_top() {
    __shared__ int s[1024];
    int tid = threadIdx.x;
    int v = (tid < NB_SCAN) ? g_bsum[tid] : 0;
    s[tid] = v;
    __syncthreads();
    #pragma unroll
    for (int o = 1; o < 1024; o <<= 1) {
        int t = (tid >= o) ? s[tid - o] : 0;
        __syncthreads();
        s[tid] += t;
        __syncthreads();
    }
    if (tid < NB_SCAN) g_bsum[tid] = s[tid] - v;
}
__global__ void k_scan_add() {
    int i = blockIdx.x * 256 + threadIdx.x;
    if (i < ROWS) {
        int o = g_off[i] + g_bsum[blockIdx.x];
        g_off[i] = o;
        g_cur[i] = o;
    }
}
__global__ void k_csr_fill(const int* __restrict__ ei) {
    int t = blockIdx.x * 256 + threadIdx.x;
    int g = t / En, e = t - g * En;
    const int* eig = ei + (size_t)g * 2 * En;
    int src = eig[e];
    int dst = eig[En + e];
    int pos = atomicAdd(&g_cur[g * Nn + dst], 1);
    g_adj[pos] = g * Nn + src;
}

// ---------------- fp16 conversion of the input features ----------------
__global__ void k_tohalf(const float* __restrict__ x0) {
    size_t i = (size_t)blockIdx.x * 256 + threadIdx.x;   // 4 floats each
    float4 v = ((const float4*)x0)[i];
    __half2 h0 = __floats2half2_rn(v.x, v.y);
    __half2 h1 = __floats2half2_rn(v.z, v.w);
    ((uint2*)g_xh)[i] = make_uint2(*(uint32_t*)&h0, *(uint32_t*)&h1);
}

// ---------------- fp16 gather aggregation (exact R10 version) -------------
__global__ void k_agg_h() {
    int w = (int)((blockIdx.x * blockDim.x + threadIdx.x) >> 5);
    int lane = threadIdx.x & 31;
    const uint2* xh = (const uint2*)g_xh;
    int base = g_off[w];
    int end = (w == ROWS - 1) ? EDGES : g_off[w + 1];
    uint2 sp = __ldg(xh + (size_t)w * 32 + lane);
    float2 f0 = __half22float2(*(__half2*)&sp.x);
    float2 f1 = __half22float2(*(__half2*)&sp.y);
    float a0 = f0.x, a1 = f0.y, a2 = f1.x, a3 = f1.y;
    for (int j0 = base; j0 < end; j0 += 32) {
        int n = end - j0;
        int sv = (lane < n) ? g_adj[j0 + lane] : 0;
        int m = min(n, 32);
        int k = 0;
        for (; k + 4 <= m; k += 4) {     // MLP=4 gather pipeline
            int s0 = __shfl_sync(0xffffffffu, sv, k);
            int s1 = __shfl_sync(0xffffffffu, sv, k + 1);
            int s2 = __shfl_sync(0xffffffffu, sv, k + 2);
            int s3 = __shfl_sync(0xffffffffu, sv, k + 3);
            uint2 p0 = __ldg(xh + (size_t)s0 * 32 + lane);
            uint2 p1 = __ldg(xh + (size_t)s1 * 32 + lane);
            uint2 p2 = __ldg(xh + (size_t)s2 * 32 + lane);
            uint2 p3 = __ldg(xh + (size_t)s3 * 32 + lane);
            float2 q;
            q = __half22float2(*(__half2*)&p0.x); a0 += q.x; a1 += q.y;
            q = __half22float2(*(__half2*)&p0.y); a2 += q.x; a3 += q.y;
            q = __half22float2(*(__half2*)&p1.x); a0 += q.x; a1 += q.y;
            q = __half22float2(*(__half2*)&p1.y); a2 += q.x; a3 += q.y;
            q = __half22float2(*(__half2*)&p2.x); a0 += q.x; a1 += q.y;
            q = __half22float2(*(__half2*)&p2.y); a2 += q.x; a3 += q.y;
            q = __half22float2(*(__half2*)&p3.x); a0 += q.x; a1 += q.y;
            q = __half22float2(*(__half2*)&p3.y); a2 += q.x; a3 += q.y;
        }
        for (; k < m; k++) {
            int s0 = __shfl_sync(0xffffffffu, sv, k);
            uint2 p0 = __ldg(xh + (size_t)s0 * 32 + lane);
            float2 q;
            q = __half22float2(*(__half2*)&p0.x); a0 += q.x; a1 += q.y;
            q = __half22float2(*(__half2*)&p0.y); a2 += q.x; a3 += q.y;
        }
    }
    __half2 h0 = __floats2half2_rn(a0, a1);
    __half2 h1 = __floats2half2_rn(a2, a3);
    ((uint2*)g_hh)[(size_t)w * 32 + lane] = make_uint2(*(uint32_t*)&h0, *(uint32_t*)&h1);
}

// ---------------- weight pre-pack (unchanged) -----
__global__ void k_pack(const float* __restrict__ Ws1, const float* __restrict__ Ws2) {
    int idx = blockIdx.x * 256 + threadIdx.x;
    if (idx >= Ln * 8192) return;
    int l = idx / 8192, r = idx % 8192;
    int kt = r >> 10, np = (r >> 7) & 7, lane = (r >> 2) & 31, j = r & 3;
    int g = lane >> 2, tig = lane & 3;
    int nt = np * 2 + (j >> 1);
    int k0 = kt * 16 + tig * 2 + ((j & 1) ? 8 : 0);
    int n = nt * 8 + g;
    const float* W1 = Ws1 + (size_t)l * Dn * Dn;
    const float* W2 = Ws2 + (size_t)l * Dn * Dn;
    __half2 h1 = __halves2half2(__float2half_rn(W1[(size_t)k0 * Dn + n]),
                                __float2half_rn(W1[(size_t)(k0 + 1) * Dn + n]));
    __half2 h2 = __halves2half2(__float2half_rn(W2[(size_t)k0 * Dn + n]),
                                __float2half_rn(W2[(size_t)(k0 + 1) * Dn + n]));
    g_W1h[idx] = *(uint32_t*)&h1;
    g_W2h[idx] = *(uint32_t*)&h2;
}

// ---------------- fused MLP (R10) + fused readout on final layer ----------
// Nn % 16 == 0, so a warp's 16 rows never straddle a graph: gid is warp-uniform.
#define A_STRIDE_B 272
#define SM_TOT (2048 + 32768 + 32768 + 128*A_STRIDE_B)   // 102400
#define MLP_GRID 296

__global__ void __launch_bounds__(256, 2)
k_mlp_mma(int layer,
          const float* __restrict__ b1, const float* __restrict__ b2,
          const float* __restrict__ lng, const float* __restrict__ lnb,
          int addRes, int writeOut) {
    extern __shared__ float sm[];
    float* b1s  = sm;
    float* b2s  = sm + 128;
    float* lngs = sm + 256;
    float* lnbs = sm + 384;
    uint32_t* wf1 = (uint32_t*)(sm + 512);      // 8192 u32
    uint32_t* wf2 = wf1 + 8192;                 // 8192 u32
    char* Ab = (char*)(wf2 + 8192);             // 128 rows x 272B

    int tid = threadIdx.x;
    int wid = tid >> 5, lane = tid & 31;
    int g = lane >> 2, tig = lane & 3;

    {   // preload weights + vectors
        const uint4* w1g = (const uint4*)(g_W1h + (size_t)layer * 8192);
        const uint4* w2g = (const uint4*)(g_W2h + (size_t)layer * 8192);
        uint4* w1s = (uint4*)wf1;
        uint4* w2s = (uint4*)wf2;
        #pragma unroll 4
        for (int i = tid; i < 2048; i += 256) { w1s[i] = __ldg(w1g + i); w2s[i] = __ldg(w2g + i); }
        if (tid < 128) {
            b1s[tid]  = __ldg(b1 + tid);
            b2s[tid]  = __ldg(b2 + tid);
            lngs[tid] = __ldg(lng + tid);
            lnbs[tid] = __ldg(lnb + tid);
        }
    }
    __syncthreads();

    const uint2* hh = (const uint2*)g_hh;
    const uint32_t* xr = (const uint32_t*)g_xh;   // residual source (fp16)
    uint32_t* xw = (uint32_t*)g_xh;               // next-layer x (fp16)

    char* rp0 = Ab + (wid * 16 + g) * A_STRIDE_B;
    char* rp1 = rp0 + 8 * A_STRIDE_B;

    float acc[16][4];

    for (int tile = blockIdx.x; tile < NT128; tile += MLP_GRID) {
        int rowbase = tile * 128;
        int wrow = rowbase + wid * 16;

        // ---- fill own 16 rows: raw fp16 copy from g_hh
        {
            char* arow = Ab + wid * 16 * A_STRIDE_B;
            #pragma unroll
            for (int i = 0; i < 16; i++) {
                uint2 p = make_uint2(0u, 0u);
                if (wrow + i < ROWS)
                    p = __ldg(hh + (size_t)(wrow + i) * 32 + lane);
                *(uint2*)(arow + i * A_STRIDE_B + lane * 8) = p;
            }
        }
        __syncwarp();

        // ---- GEMM1
        #pragma unroll
        for (int nt = 0; nt < 16; nt++) { acc[nt][0]=acc[nt][1]=acc[nt][2]=acc[nt][3]=0.f; }
        #pragma unroll
        for (int kt = 0; kt < 8; kt++) {
            uint32_t a0 = *(const uint32_t*)(rp0 + kt*32 + tig*4);
            uint32_t a1 = *(const uint32_t*)(rp1 + kt*32 + tig*4);
            uint32_t a2 = *(const uint32_t*)(rp0 + kt*32 + tig*4 + 16);
            uint32_t a3 = *(const uint32_t*)(rp1 + kt*32 + tig*4 + 16);
            const uint4* wfb = (const uint4*)wf1 + kt * 8 * 32 + lane;
            #pragma unroll
            for (int np = 0; np < 8; np++) {
                uint4 b = wfb[np * 32];
                mma_f16(acc[2*np],   a0, a1, a2, a3, b.x, b.y);
                mma_f16(acc[2*np+1], a0, a1, a2, a3, b.z, b.w);
            }
        }

        // ---- relu(+b1) -> fp16, stage back into own A rows
        __syncwarp();
        #pragma unroll
        for (int nt = 0; nt < 16; nt++) {
            float2 bb = *(float2*)&b1s[nt*8 + tig*2];
            __half2 lo = __floats2half2_rn(fmaxf(acc[nt][0] + bb.x, 0.f),
                                           fmaxf(acc[nt][1] + bb.y, 0.f));
            __half2 hi = __floats2half2_rn(fmaxf(acc[nt][2] + bb.x, 0.f),
                                           fmaxf(acc[nt][3] + bb.y, 0.f));
            *(uint32_t*)(rp0 + nt*16 + tig*4) = *(uint32_t*)&lo;
            *(uint32_t*)(rp1 + nt*16 + tig*4) = *(uint32_t*)&hi;
        }
        __syncwarp();

        // ---- GEMM2
        #pragma unroll
        for (int nt = 0; nt < 16; nt++) { acc[nt][0]=acc[nt][1]=acc[nt][2]=acc[nt][3]=0.f; }
        #pragma unroll
        for (int kt = 0; kt < 8; kt++) {
            uint32_t a0 = *(const uint32_t*)(rp0 + kt*32 + tig*4);
            uint32_t a1 = *(const uint32_t*)(rp1 + kt*32 + tig*4);
            uint32_t a2 = *(const uint32_t*)(rp0 + kt*32 + tig*4 + 16);
            uint32_t a3 = *(const uint32_t*)(rp1 + kt*32 + tig*4 + 16);
            const uint4* wfb = (const uint4*)wf2 + kt * 8 * 32 + lane;
            #pragma unroll
            for (int np = 0; np < 8; np++) {
                uint4 b = wfb[np * 32];
                mma_f16(acc[2*np],   a0, a1, a2, a3, b.x, b.y);
                mma_f16(acc[2*np+1], a0, a1, a2, a3, b.z, b.w);
            }
        }

        // ---- epilogue: +b2 (+fp16 residual), LN over quad
        {
            int r0g = wrow + g, r1g = wrow + g + 8;
            bool v0 = r0g < ROWS, v1 = r1g < ROWS;
            float s0 = 0.f, ss0 = 0.f, s1 = 0.f, ss1 = 0.f;
            #pragma unroll
            for (int nt = 0; nt < 16; nt++) {
                int c = nt*8 + tig*2;
                float2 bb = *(float2*)&b2s[c];
                acc[nt][0] += bb.x; acc[nt][1] += bb.y;
                acc[nt][2] += bb.x; acc[nt][3] += bb.y;
                if (addRes) {
                    if (v0) {
                        uint32_t rv = __ldg(xr + (((size_t)r0g * Dn + c) >> 1));
                        float2 q = __half22float2(*(__half2*)&rv);
                        acc[nt][0] += q.x; acc[nt][1] += q.y;
                    }
                    if (v1) {
                        uint32_t rv = __ldg(xr + (((size_t)r1g * Dn + c) >> 1));
                        float2 q = __half22float2(*(__half2*)&rv);
                        acc[nt][2] += q.x; acc[nt][3] += q.y;
                    }
                }
                s0  += acc[nt][0] + acc[nt][1];
                ss0 += acc[nt][0]*acc[nt][0] + acc[nt][1]*acc[nt][1];
                s1  += acc[nt][2] + acc[nt][3];
                ss1 += acc[nt][2]*acc[nt][2] + acc[nt][3]*acc[nt][3];
            }
            s0  += __shfl_xor_sync(0xffffffffu, s0, 1);  s0  += __shfl_xor_sync(0xffffffffu, s0, 2);
            ss0 += __shfl_xor_sync(0xffffffffu, ss0, 1); ss0 += __shfl_xor_sync(0xffffffffu, ss0, 2);
            s1  += __shfl_xor_sync(0xffffffffu, s1, 1);  s1  += __shfl_xor_sync(0xffffffffu, s1, 2);
            ss1 += __shfl_xor_sync(0xffffffffu, ss1, 1); ss1 += __shfl_xor_sync(0xffffffffu, ss1, 2);
            float mu0 = s0 * (1.f/128.f), mu1 = s1 * (1.f/128.f);
            float iv0 = rsqrtf(ss0 * (1.f/128.f) - mu0*mu0 + LN_EPS);
            float iv1 = rsqrtf(ss1 * (1.f/128.f) - mu1*mu1 + LN_EPS);

            if (writeOut) {
                // fused graph readout: LN output summed over warp rows -> g_gvec
                #pragma unroll
                for (int nt = 0; nt < 16; nt++) {
                    int c = nt*8 + tig*2;
                    float2 gg = *(float2*)&lngs[c];
                    float2 bb = *(float2*)&lnbs[c];
                    float x0v = (acc[nt][0] - mu0) * iv0 * gg.x + bb.x;
                    float y0v = (acc[nt][1] - mu0) * iv0 * gg.y + bb.y;
                    float x1v = (acc[nt][2] - mu1) * iv1 * gg.x + bb.x;
                    float y1v = (acc[nt][3] - mu1) * iv1 * gg.y + bb.y;
                    float cx = (v0 ? x0v : 0.f) + (v1 ? x1v : 0.f);
                    float cy = (v0 ? y0v : 0.f) + (v1 ? y1v : 0.f);
                    cx += __shfl_xor_sync(0xffffffffu, cx, 4);
                    cx += __shfl_xor_sync(0xffffffffu, cx, 8);
                    cx += __shfl_xor_sync(0xffffffffu, cx, 16);
                    cy += __shfl_xor_sync(0xffffffffu, cy, 4);
                    cy += __shfl_xor_sync(0xffffffffu, cy, 8);
                    cy += __shfl_xor_sync(0xffffffffu, cy, 16);
                    acc[nt][0] = cx; acc[nt][1] = cy;
                }
                if (g == 0 && wrow < ROWS) {
                    int gid = wrow / Nn;    // warp-uniform (Nn % 16 == 0)
                    #pragma unroll
                    for (int nt = 0; nt < 16; nt++) {
                        int c = nt*8 + tig*2;
                        atomicAdd(&g_gvec[gid * Dn + c],     acc[nt][0]);
                        atomicAdd(&g_gvec[gid * Dn + c + 1], acc[nt][1]);
                    }
                }
            } else {
                #pragma unroll
                for (int nt = 0; nt < 16; nt++) {
                    int c = nt*8 + tig*2;
                    float2 gg = *(float2*)&lngs[c];
                    float2 bb = *(float2*)&lnbs[c];
                    if (v0) {
                        float2 ov;
                        ov.x = (acc[nt][0] - mu0) * iv0 * gg.x + bb.x;
                        ov.y = (acc[nt][1] - mu0) * iv0 * gg.y + bb.y;
                        __half2 hv = __floats2half2_rn(ov.x, ov.y);
                        xw[((size_t)r0g * Dn + c) >> 1] = *(uint32_t*)&hv;
                    }
                    if (v1) {
                        float2 ov;
                        ov.x = (acc[nt][2] - mu1) * iv1 * gg.x + bb.x;
                        ov.y = (acc[nt][3] - mu1) * iv1 * gg.y + bb.y;
                        __half2 hv = __floats2half2_rn(ov.x, ov.y);
                        xw[((size_t)r1g * Dn + c) >> 1] = *(uint32_t*)&hv;
                    }
                }
            }
        }
        __syncwarp();
    }
}

// ---------------- attention (reads g_gvec) ----------------
__global__ void k_zero() { g_gvec[threadIdx.x] = 0.f; }

__global__ void k_att(const float* __restrict__ w1, const float* __restrict__ w2,
                      float* __restrict__ out) {
    __shared__ float gm[Gn * Dn];
    __shared__ float sup[AHn * Gn];
    __shared__ float att[NEx * Gn];
    int tid = threadIdx.x;
    for (int i = tid; i < Gn * Dn; i += 256) gm[i] = g_gvec[i];
    __syncthreads();
    if (tid < AHn * Gn) {
        int ah = tid >> 2, gr = tid & 3;
        float s = 0.f;
        #pragma unroll 8
        for (int d = 0; d < Dn; d++) s = fmaf(__ldg(w1 + ah * Dn + d), gm[gr * Dn + d], s);
        sup[tid] = tanhf(s);
    }
    __syncthreads();
    if (tid < NEx * Gn) {
        int e = tid >> 2, gr = tid & 3;
        float s = 0.f;
        #pragma unroll 8
        for (int a = 0; a < AHn; a++) s = fmaf(__ldg(w2 + e * AHn + a), sup[a * 4 + gr], s);
        att[tid] = s;
    }
    __syncthreads();
    if (tid < NEx) {
        float m = -1e30f;
        #pragma unroll
        for (int gr = 0; gr < 4; gr++) m = fmaxf(m, att[tid * 4 + gr]);
        float ex[4]; float sum = 0.f;
        #pragma unroll
        for (int gr = 0; gr < 4; gr++) { ex[gr] = expf(att[tid * 4 + gr] - m); sum += ex[gr]; }
        float inv = 1.f / sum;
        #pragma unroll
        for (int gr = 0; gr < 4; gr++) att[tid * 4 + gr] = ex[gr] * inv;
    }
    __syncthreads();
    for (int o = tid; o < NEx * Dn; o += 256) {
        int e = o >> 7, d = o & 127;
        float s = 0.f;
        #pragma unroll
        for (int gr = 0; gr < 4; gr++) s = fmaf(att[e * 4 + gr], gm[gr * Dn + d], s);
        out[o] = s;
    }
}

// ---------------------------------------------------------------------------
extern "C" void kernel_launch(void* const* d_in, const int* in_sizes, int n_in,
                              void* d_out, int out_size) {
    const float* x0  = (const float*)d_in[0];
    const int*   ei  = (const int*)d_in[1];
    const float* Ws1 = (const float*)d_in[3];
    const float* bs1 = (const float*)d_in[4];
    const float* Ws2 = (const float*)d_in[5];
    const float* bs2 = (const float*)d_in[6];
    const float* lng = (const float*)d_in[7];
    const float* lnb = (const float*)d_in[8];
    const float* aw1 = (const float*)d_in[9];
    const float* aw2 = (const float*)d_in[10];
    float* out = (float*)d_out;

    cudaFuncSetAttribute(k_mlp_mma, cudaFuncAttributeMaxDynamicSharedMemorySize, SM_TOT);

    k_pack<<<(Ln * 8192 + 255) / 256, 256>>>(Ws1, Ws2);

    // CSR build (once per launch; edge index is constant input)
    k_csr_zero<<<NB_SCAN, 256>>>();
    k_csr_count<<<EDGES / 256, 256>>>(ei);
    k_scan_block<<<NB_SCAN, 256>>>();
    k_scan_top<<<1, 1024>>>();
    k_scan_add<<<NB_SCAN, 256>>>();
    k_csr_fill<<<EDGES / 256, 256>>>(ei);

    // fp16 image of the input features
    k_tohalf<<<(ROWS * Dn / 4) / 256, 256>>>(x0);

    k_zero<<<1, Gn * Dn>>>();   // g_gvec accumulated by final MLP layer

    for (int l = 0; l < Ln; l++) {
        k_agg_h<<<ROWS / 8, 256>>>();
        k_mlp_mma<<<MLP_GRID, 256, SM_TOT>>>(l,
                                             bs1 + l * Dn, bs2 + l * Dn,
                                             lng + l * Dn, lnb + l * Dn,
                                             (l < Ln - 1) ? 1 : 0,
                                             (l == Ln - 1) ? 1 : 0);
    }
    k_att<<<1, 256>>>(aw1, aw2, out);
}

// round 14
// speedup vs baseline: 1.1167x; 1.0303x over previous
#include <cuda_runtime.h>
#include <cuda_fp16.h>
#include <cstdint>

#define Gn 4
#define Nn 50000
#define En 400000
#define Dn 128
#define Ln 3
#define NEx 8
#define AHn 64
#define ROWS (Gn*Nn)
#define EDGES (Gn*En)
#define NT128 ((ROWS + 127) / 128)
#define LN_EPS 1e-5f
#define NB_SCAN 782              // ceil(ROWS/256)

// ---------------- scratch (static, allocation-free) ----------------
__device__ __half g_xh[(size_t)ROWS * Dn];    // fp16 current-layer features
__device__ __half g_hh[(size_t)ROWS * Dn];    // fp16 h = x + agg
__device__ float g_gvec[Gn * Dn];
__device__ uint32_t g_W1h[Ln * 8192];
__device__ uint32_t g_W2h[Ln * 8192];
// CSR scratch
__device__ int g_cnt[ROWS];
__device__ int g_off[ROWS];
__device__ int g_cur[ROWS];
__device__ int g_adj[EDGES];
__device__ int g_bsum[NB_SCAN];

__device__ __forceinline__ void mma_f16(float* c, uint32_t a0, uint32_t a1,
                                        uint32_t a2, uint32_t a3,
                                        uint32_t b0, uint32_t b1) {
    asm volatile(
        "mma.sync.aligned.m16n8k16.row.col.f32.f16.f16.f32 "
        "{%0,%1,%2,%3}, {%4,%5,%6,%7}, {%8,%9}, {%0,%1,%2,%3};"
        : "+f"(c[0]), "+f"(c[1]), "+f"(c[2]), "+f"(c[3])
        : "r"(a0), "r"(a1), "r"(a2), "r"(a3), "r"(b0), "r"(b1));
}

// ---------------- CSR build (g_cnt zeroed via cudaMemsetAsync) -----------
__global__ void k_csr_count(const int* __restrict__ ei) {
    int t = blockIdx.x * 256 + threadIdx.x;
    int g = t / En, e = t - g * En;
    int dst = ei[(size_t)g * 2 * En + En + e];
    atomicAdd(&g_cnt[g * Nn + dst], 1);
}
__global__ void k_scan_block() {
    __shared__ int s[256];
    int i = blockIdx.x * 256 + threadIdx.x;
    int v = (i < ROWS) ? g_cnt[i] : 0;
    s[threadIdx.x] = v;
    __syncthreads();
    #pragma unroll
    for (int o = 1; o < 256; o <<= 1) {
        int t = (threadIdx.x >= o) ? s[threadIdx.x - o] : 0;
        __syncthreads();
        s[threadIdx.x] += t;
        __syncthreads();
    }
    if (i < ROWS) g_off[i] = s[threadIdx.x] - v;
    if (threadIdx.x == 255) g_bsum[blockIdx.x] = s[255];
}
__global__ void k_scan_top() {
    __shared__ int s[1024];
    int tid = threadIdx.x;
    int v = (tid < NB_SCAN) ? g_bsum[tid] : 0;
    s[tid] = v;
    __syncthreads();
    #pragma unroll
    for (int o = 1; o < 1024; o <<= 1) {
        int t = (tid >= o) ? s[tid - o] : 0;
        __syncthreads();
        s[tid] += t;
        __syncthreads();
    }
    if (tid < NB_SCAN) g_bsum[tid] = s[tid] - v;
}
__global__ void k_scan_add() {
    int i = blockIdx.x * 256 + threadIdx.x;
    if (i < ROWS) {
        int o = g_off[i] + g_bsum[blockIdx.x];
        g_off[i] = o;
        g_cur[i] = o;
    }
}
__global__ void k_csr_fill(const int* __restrict__ ei) {
    int t = blockIdx.x * 256 + threadIdx.x;
    int g = t / En, e = t - g * En;
    const int* eig = ei + (size_t)g * 2 * En;
    int src = eig[e];
    int dst = eig[En + e];
    int pos = atomicAdd(&g_cur[g * Nn + dst], 1);
    g_adj[pos] = g * Nn + src;
}

// ---------------- merged: weight pre-pack + fp16 feature conversion ------
#define PACK_BLOCKS ((Ln * 8192 + 255) / 256)          // 96
#define TOHALF_BLOCKS ((ROWS * Dn / 4) / 256)          // 25000
__global__ void k_prep(const float* __restrict__ x0,
                       const float* __restrict__ Ws1, const float* __restrict__ Ws2) {
    if (blockIdx.x < PACK_BLOCKS) {
        int idx = blockIdx.x * 256 + threadIdx.x;
        if (idx >= Ln * 8192) return;
        int l = idx / 8192, r = idx % 8192;
        int kt = r >> 10, np = (r >> 7) & 7, lane = (r >> 2) & 31, j = r & 3;
        int g = lane >> 2, tig = lane & 3;
        int nt = np * 2 + (j >> 1);
        int k0 = kt * 16 + tig * 2 + ((j & 1) ? 8 : 0);
        int n = nt * 8 + g;
        const float* W1 = Ws1 + (size_t)l * Dn * Dn;
        const float* W2 = Ws2 + (size_t)l * Dn * Dn;
        __half2 h1 = __halves2half2(__float2half_rn(W1[(size_t)k0 * Dn + n]),
                                    __float2half_rn(W1[(size_t)(k0 + 1) * Dn + n]));
        __half2 h2 = __halves2half2(__float2half_rn(W2[(size_t)k0 * Dn + n]),
                                    __float2half_rn(W2[(size_t)(k0 + 1) * Dn + n]));
        g_W1h[idx] = *(uint32_t*)&h1;
        g_W2h[idx] = *(uint32_t*)&h2;
    } else {
        size_t i = (size_t)(blockIdx.x - PACK_BLOCKS) * 256 + threadIdx.x;
        float4 v = ((const float4*)x0)[i];
        __half2 h0 = __floats2half2_rn(v.x, v.y);
        __half2 h1 = __floats2half2_rn(v.z, v.w);
        ((uint2*)g_xh)[i] = make_uint2(*(uint32_t*)&h0, *(uint32_t*)&h1);
    }
}

// ---------------- fp16 gather aggregation (exact R10 version) -------------
__global__ void k_agg_h() {
    int w = (int)((blockIdx.x * blockDim.x + threadIdx.x) >> 5);
    int lane = threadIdx.x & 31;
    const uint2* xh = (const uint2*)g_xh;
    int base = g_off[w];
    int end = (w == ROWS - 1) ? EDGES : g_off[w + 1];
    uint2 sp = __ldg(xh + (size_t)w * 32 + lane);
    float2 f0 = __half22float2(*(__half2*)&sp.x);
    float2 f1 = __half22float2(*(__half2*)&sp.y);
    float a0 = f0.x, a1 = f0.y, a2 = f1.x, a3 = f1.y;
    for (int j0 = base; j0 < end; j0 += 32) {
        int n = end - j0;
        int sv = (lane < n) ? g_adj[j0 + lane] : 0;
        int m = min(n, 32);
        int k = 0;
        for (; k + 4 <= m; k += 4) {
            int s0 = __shfl_sync(0xffffffffu, sv, k);
            int s1 = __shfl_sync(0xffffffffu, sv, k + 1);
            int s2 = __shfl_sync(0xffffffffu, sv, k + 2);
            int s3 = __shfl_sync(0xffffffffu, sv, k + 3);
            uint2 p0 = __ldg(xh + (size_t)s0 * 32 + lane);
            uint2 p1 = __ldg(xh + (size_t)s1 * 32 + lane);
            uint2 p2 = __ldg(xh + (size_t)s2 * 32 + lane);
            uint2 p3 = __ldg(xh + (size_t)s3 * 32 + lane);
            float2 q;
            q = __half22float2(*(__half2*)&p0.x); a0 += q.x; a1 += q.y;
            q = __half22float2(*(__half2*)&p0.y); a2 += q.x; a3 += q.y;
            q = __half22float2(*(__half2*)&p1.x); a0 += q.x; a1 += q.y;
            q = __half22float2(*(__half2*)&p1.y); a2 += q.x; a3 += q.y;
            q = __half22float2(*(__half2*)&p2.x); a0 += q.x; a1 += q.y;
            q = __half22float2(*(__half2*)&p2.y); a2 += q.x; a3 += q.y;
            q = __half22float2(*(__half2*)&p3.x); a0 += q.x; a1 += q.y;
            q = __half22float2(*(__half2*)&p3.y); a2 += q.x; a3 += q.y;
        }
        for (; k < m; k++) {
            int s0 = __shfl_sync(0xffffffffu, sv, k);
            uint2 p0 = __ldg(xh + (size_t)s0 * 32 + lane);
            float2 q;
            q = __half22float2(*(__half2*)&p0.x); a0 += q.x; a1 += q.y;
            q = __half22float2(*(__half2*)&p0.y); a2 += q.x; a3 += q.y;
        }
    }
    __half2 h0 = __floats2half2_rn(a0, a1);
    __half2 h1 = __floats2half2_rn(a2, a3);
    ((uint2*)g_hh)[(size_t)w * 32 + lane] = make_uint2(*(uint32_t*)&h0, *(uint32_t*)&h1);
}

// ---------------- fused MLP + readout, cp.async tile-pipelined A-fill -----
#define A_STRIDE_B 272
#define SM_TOT (2048 + 32768 + 32768 + 128*A_STRIDE_B)   // 102400
#define MLP_GRID 296

__global__ void __launch_bounds__(256, 2)
k_mlp_mma(int layer,
          const float* __restrict__ b1, const float* __restrict__ b2,
          const float* __restrict__ lng, const float* __restrict__ lnb,
          int addRes, int writeOut) {
    extern __shared__ float sm[];
    float* b1s  = sm;
    float* b2s  = sm + 128;
    float* lngs = sm + 256;
    float* lnbs = sm + 384;
    uint32_t* wf1 = (uint32_t*)(sm + 512);      // 8192 u32
    uint32_t* wf2 = wf1 + 8192;                 // 8192 u32
    char* Ab = (char*)(wf2 + 8192);             // 128 rows x 272B

    int tid = threadIdx.x;
    int wid = tid >> 5, lane = tid & 31;
    int g = lane >> 2, tig = lane & 3;

    {   // preload weights + vectors
        const uint4* w1g = (const uint4*)(g_W1h + (size_t)layer * 8192);
        const uint4* w2g = (const uint4*)(g_W2h + (size_t)layer * 8192);
        uint4* w1s = (uint4*)wf1;
        uint4* w2s = (uint4*)wf2;
        #pragma unroll 4
        for (int i = tid; i < 2048; i += 256) { w1s[i] = __ldg(w1g + i); w2s[i] = __ldg(w2g + i); }
        if (tid < 128) {
            b1s[tid]  = __ldg(b1 + tid);
            b2s[tid]  = __ldg(b2 + tid);
            lngs[tid] = __ldg(lng + tid);
            lnbs[tid] = __ldg(lnb + tid);
        }
    }
    __syncthreads();

    const uint2* hh = (const uint2*)g_hh;
    const uint32_t* xr = (const uint32_t*)g_xh;   // residual source (fp16)
    uint32_t* xw = (uint32_t*)g_xh;               // next-layer x (fp16)

    char* rp0 = Ab + (wid * 16 + g) * A_STRIDE_B;
    char* rp1 = rp0 + 8 * A_STRIDE_B;
    char* arow = Ab + wid * 16 * A_STRIDE_B;

    float acc[16][4];

    // cp.async fill of this warp's 16 rows for tile t (overlappable)
    auto fill_tile = [&](int t) {
        int wr = t * 128 + wid * 16;
        #pragma unroll
        for (int i = 0; i < 16; i++) {
            char* dst = arow + i * A_STRIDE_B + lane * 8;
            int row = wr + i;
            if (row < ROWS) {
                uint32_t sa = (uint32_t)__cvta_generic_to_shared(dst);
                asm volatile("cp.async.ca.shared.global [%0], [%1], 8;"
                             :: "r"(sa), "l"(hh + (size_t)row * 32 + lane) : "memory");
            } else {
                *(uint2*)dst = make_uint2(0u, 0u);
            }
        }
        asm volatile("cp.async.commit_group;" ::: "memory");
    };

    int tile = blockIdx.x;
    if (tile < NT128) fill_tile(tile);

    for (; tile < NT128; tile += MLP_GRID) {
        int wrow = tile * 128 + wid * 16;

        asm volatile("cp.async.wait_group 0;" ::: "memory");
        __syncwarp();

        // ---- GEMM1
        #pragma unroll
        for (int nt = 0; nt < 16; nt++) { acc[nt][0]=acc[nt][1]=acc[nt][2]=acc[nt][3]=0.f; }
        #pragma unroll
        for (int kt = 0; kt < 8; kt++) {
            uint32_t a0 = *(const uint32_t*)(rp0 + kt*32 + tig*4);
            uint32_t a1 = *(const uint32_t*)(rp1 + kt*32 + tig*4);
            uint32_t a2 = *(const uint32_t*)(rp0 + kt*32 + tig*4 + 16);
            uint32_t a3 = *(const uint32_t*)(rp1 + kt*32 + tig*4 + 16);
            const uint4* wfb = (const uint4*)wf1 + kt * 8 * 32 + lane;
            #pragma unroll
            for (int np = 0; np < 8; np++) {
                uint4 b = wfb[np * 32];
                mma_f16(acc[2*np],   a0, a1, a2, a3, b.x, b.y);
                mma_f16(acc[2*np+1], a0, a1, a2, a3, b.z, b.w);
            }
        }

        // ---- relu(+b1) -> fp16, stage back into own A rows
        __syncwarp();
        #pragma unroll
        for (int nt = 0; nt < 16; nt++) {
            float2 bb = *(float2*)&b1s[nt*8 + tig*2];
            __half2 lo = __floats2half2_rn(fmaxf(acc[nt][0] + bb.x, 0.f),
                                           fmaxf(acc[nt][1] + bb.y, 0.f));
            __half2 hi = __floats2half2_rn(fmaxf(acc[nt][2] + bb.x, 0.f),
                                           fmaxf(acc[nt][3] + bb.y, 0.f));
            *(uint32_t*)(rp0 + nt*16 + tig*4) = *(uint32_t*)&lo;
            *(uint32_t*)(rp1 + nt*16 + tig*4) = *(uint32_t*)&hi;
        }
        __syncwarp();

        // ---- GEMM2
        #pragma unroll
        for (int nt = 0; nt < 16; nt++) { acc[nt][0]=acc[nt][1]=acc[nt][2]=acc[nt][3]=0.f; }
        #pragma unroll
        for (int kt = 0; kt < 8; kt++) {
            uint32_t a0 = *(const uint32_t*)(rp0 + kt*32 + tig*4);
            uint32_t a1 = *(const uint32_t*)(rp1 + kt*32 + tig*4);
            uint32_t a2 = *(const uint32_t*)(rp0 + kt*32 + tig*4 + 16);
            uint32_t a3 = *(const uint32_t*)(rp1 + kt*32 + tig*4 + 16);
            const uint4* wfb = (const uint4*)wf2 + kt * 8 * 32 + lane;
            #pragma unroll
            for (int np = 0; np < 8; np++) {
                uint4 b = wfb[np * 32];
                mma_f16(acc[2*np],   a0, a1, a2, a3, b.x, b.y);
                mma_f16(acc[2*np+1], a0, a1, a2, a3, b.z, b.w);
            }
        }
        __syncwarp();   // all reads of Ab complete before next-tile cp.async

        // ---- prefetch next tile's A rows (overlaps the epilogue below)
        if (tile + MLP_GRID < NT128) fill_tile(tile + MLP_GRID);

        // ---- epilogue: +b2 (+fp16 residual), LN over quad
        {
            int r0g = wrow + g, r1g = wrow + g + 8;
            bool v0 = r0g < ROWS, v1 = r1g < ROWS;
            float s0 = 0.f, ss0 = 0.f, s1 = 0.f, ss1 = 0.f;
            #pragma unroll
            for (int nt = 0; nt < 16; nt++) {
                int c = nt*8 + tig*2;
                float2 bb = *(float2*)&b2s[c];
                acc[nt][0] += bb.x; acc[nt][1] += bb.y;
                acc[nt][2] += bb.x; acc[nt][3] += bb.y;
                if (addRes) {
                    if (v0) {
                        uint32_t rv = __ldg(xr + (((size_t)r0g * Dn + c) >> 1));
                        float2 q = __half22float2(*(__half2*)&rv);
                        acc[nt][0] += q.x; acc[nt][1] += q.y;
                    }
                    if (v1) {
                        uint32_t rv = __ldg(xr + (((size_t)r1g * Dn + c) >> 1));
                        float2 q = __half22float2(*(__half2*)&rv);
                        acc[nt][2] += q.x; acc[nt][3] += q.y;
                    }
                }
                s0  += acc[nt][0] + acc[nt][1];
                ss0 += acc[nt][0]*acc[nt][0] + acc[nt][1]*acc[nt][1];
                s1  += acc[nt][2] + acc[nt][3];
                ss1 += acc[nt][2]*acc[nt][2] + acc[nt][3]*acc[nt][3];
            }
            s0  += __shfl_xor_sync(0xffffffffu, s0, 1);  s0  += __shfl_xor_sync(0xffffffffu, s0, 2);
            ss0 += __shfl_xor_sync(0xffffffffu, ss0, 1); ss0 += __shfl_xor_sync(0xffffffffu, ss0, 2);
            s1  += __shfl_xor_sync(0xffffffffu, s1, 1);  s1  += __shfl_xor_sync(0xffffffffu, s1, 2);
            ss1 += __shfl_xor_sync(0xffffffffu, ss1, 1); ss1 += __shfl_xor_sync(0xffffffffu, ss1, 2);
            float mu0 = s0 * (1.f/128.f), mu1 = s1 * (1.f/128.f);
            float iv0 = rsqrtf(ss0 * (1.f/128.f) - mu0*mu0 + LN_EPS);
            float iv1 = rsqrtf(ss1 * (1.f/128.f) - mu1*mu1 + LN_EPS);

            if (writeOut) {
                // fused graph readout: LN output summed over warp rows -> g_gvec
                #pragma unroll
                for (int nt = 0; nt < 16; nt++) {
                    int c = nt*8 + tig*2;
                    float2 gg = *(float2*)&lngs[c];
                    float2 bb = *(float2*)&lnbs[c];
                    float x0v = (acc[nt][0] - mu0) * iv0 * gg.x + bb.x;
                    float y0v = (acc[nt][1] - mu0) * iv0 * gg.y + bb.y;
                    float x1v = (acc[nt][2] - mu1) * iv1 * gg.x + bb.x;
                    float y1v = (acc[nt][3] - mu1) * iv1 * gg.y + bb.y;
                    float cx = (v0 ? x0v : 0.f) + (v1 ? x1v : 0.f);
                    float cy = (v0 ? y0v : 0.f) + (v1 ? y1v : 0.f);
                    cx += __shfl_xor_sync(0xffffffffu, cx, 4);
                    cx += __shfl_xor_sync(0xffffffffu, cx, 8);
                    cx += __shfl_xor_sync(0xffffffffu, cx, 16);
                    cy += __shfl_xor_sync(0xffffffffu, cy, 4);
                    cy += __shfl_xor_sync(0xffffffffu, cy, 8);
                    cy += __shfl_xor_sync(0xffffffffu, cy, 16);
                    acc[nt][0] = cx; acc[nt][1] = cy;
                }
                if (g == 0 && wrow < ROWS) {
                    int gid = wrow / Nn;    // warp-uniform (Nn % 16 == 0)
                    #pragma unroll
                    for (int nt = 0; nt < 16; nt++) {
                        int c = nt*8 + tig*2;
                        atomicAdd(&g_gvec[gid * Dn + c],     acc[nt][0]);
                        atomicAdd(&g_gvec[gid * Dn + c + 1], acc[nt][1]);
                    }
                }
            } else {
                #pragma unroll
                for (int nt = 0; nt < 16; nt++) {
                    int c = nt*8 + tig*2;
                    float2 gg = *(float2*)&lngs[c];
                    float2 bb = *(float2*)&lnbs[c];
                    if (v0) {
                        float2 ov;
                        ov.x = (acc[nt][0] - mu0) * iv0 * gg.x + bb.x;
                        ov.y = (acc[nt][1] - mu0) * iv0 * gg.y + bb.y;
                        __half2 hv = __floats2half2_rn(ov.x, ov.y);
                        xw[((size_t)r0g * Dn + c) >> 1] = *(uint32_t*)&hv;
                    }
                    if (v1) {
                        float2 ov;
                        ov.x = (acc[nt][2] - mu1) * iv1 * gg.x + bb.x;
                        ov.y = (acc[nt][3] - mu1) * iv1 * gg.y + bb.y;
                        __half2 hv = __floats2half2_rn(ov.x, ov.y);
                        xw[((size_t)r1g * Dn + c) >> 1] = *(uint32_t*)&hv;
                    }
                }
            }
        }
        __syncwarp();
    }
}

// ---------------- attention (reads g_gvec) ----------------
__global__ void k_att(const float* __restrict__ w1, const float* __restrict__ w2,
                      float* __restrict__ out) {
    __shared__ float gm[Gn * Dn];
    __shared__ float sup[AHn * Gn];
    __shared__ float att[NEx * Gn];
    int tid = threadIdx.x;
    for (int i = tid; i < Gn * Dn; i += 256) gm[i] = g_gvec[i];
    __syncthreads();
    if (tid < AHn * Gn) {
        int ah = tid >> 2, gr = tid & 3;
        float s = 0.f;
        #pragma unroll 8
        for (int d = 0; d < Dn; d++) s = fmaf(__ldg(w1 + ah * Dn + d), gm[gr * Dn + d], s);
        sup[tid] = tanhf(s);
    }
    __syncthreads();
    if (tid < NEx * Gn) {
        int e = tid >> 2, gr = tid & 3;
        float s = 0.f;
        #pragma unroll 8
        for (int a = 0; a < AHn; a++) s = fmaf(__ldg(w2 + e * AHn + a), sup[a * 4 + gr], s);
        att[tid] = s;
    }
    __syncthreads();
    if (tid < NEx) {
        float m = -1e30f;
        #pragma unroll
        for (int gr = 0; gr < 4; gr++) m = fmaxf(m, att[tid * 4 + gr]);
        float ex[4]; float sum = 0.f;
        #pragma unroll
        for (int gr = 0; gr < 4; gr++) { ex[gr] = expf(att[tid * 4 + gr] - m); sum += ex[gr]; }
        float inv = 1.f / sum;
        #pragma unroll
        for (int gr = 0; gr < 4; gr++) att[tid * 4 + gr] = ex[gr] * inv;
    }
    __syncthreads();
    for (int o = tid; o < NEx * Dn; o += 256) {
        int e = o >> 7, d = o & 127;
        float s = 0.f;
        #pragma unroll
        for (int gr = 0; gr < 4; gr++) s = fmaf(att[e * 4 + gr], gm[gr * Dn + d], s);
        out[o] = s;
    }
}

// ---------------------------------------------------------------------------
extern "C" void kernel_launch(void* const* d_in, const int* in_sizes, int n_in,
                              void* d_out, int out_size) {
    const float* x0  = (const float*)d_in[0];
    const int*   ei  = (const int*)d_in[1];
    const float* Ws1 = (const float*)d_in[3];
    const float* bs1 = (const float*)d_in[4];
    const float* Ws2 = (const float*)d_in[5];
    const float* bs2 = (const float*)d_in[6];
    const float* lng = (const float*)d_in[7];
    const float* lnb = (const float*)d_in[8];
    const float* aw1 = (const float*)d_in[9];
    const float* aw2 = (const float*)d_in[10];
    float* out = (float*)d_out;

    cudaFuncSetAttribute(k_mlp_mma, cudaFuncAttributeMaxDynamicSharedMemorySize, SM_TOT);

    void* p_cnt = nullptr;
    void* p_gvec = nullptr;
    cudaGetSymbolAddress(&p_cnt, g_cnt);
    cudaGetSymbolAddress(&p_gvec, g_gvec);

    // zero counters + graph-vector accumulator (graph-capturable memsets)
    cudaMemsetAsync(p_cnt, 0, ROWS * sizeof(int));
    cudaMemsetAsync(p_gvec, 0, Gn * Dn * sizeof(float));

    // merged weight-pack + fp16 feature image
    k_prep<<<PACK_BLOCKS + TOHALF_BLOCKS, 256>>>(x0, Ws1, Ws2);

    // CSR build (once per launch; edge index is constant input)
    k_csr_count<<<EDGES / 256, 256>>>(ei);
    k_scan_block<<<NB_SCAN, 256>>>();
    k_scan_top<<<1, 1024>>>();
    k_scan_add<<<NB_SCAN, 256>>>();
    k_csr_fill<<<EDGES / 256, 256>>>(ei);

    for (int l = 0; l < Ln; l++) {
        k_agg_h<<<ROWS / 8, 256>>>();
        k_mlp_mma<<<MLP_GRID, 256, SM_TOT>>>(l,
                                             bs1 + l * Dn, bs2 + l * Dn,
                                             lng + l * Dn, lnb + l * Dn,
                                             (l < Ln - 1) ? 1 : 0,
                                             (l == Ln - 1) ? 1 : 0);
    }
    k_att<<<1, 256>>>(aw1, aw2, out);
}